// round 13
// baseline (speedup 1.0000x reference)
#include <cuda_runtime.h>
#include <cstdint>

#define NN   50000
#define NE   1000000
#define INC  256
#define F1   256   // HEADS * HID_CH
#define OC   3

// ---------------- scratch (device globals; no allocation allowed) ----------------
__device__ __align__(16) float g_h1[NN * F1];     // layer1 features h = x@W1
__device__ __align__(16) float g_out1[NN * F1];   // unnormalized aggregation
__device__ __align__(8)  float g_als1[NN * 2];
__device__ __align__(8)  float g_ald1[NN * 2];
__device__ __align__(8)  float g_den1[NN * 2];
__device__ __align__(16) float g_h2[NN * 4];      // layer2 features, .w = 1 for denom
__device__ float g_als2[NN];
__device__ float g_ald2[NN];
__device__ __align__(16) float g_out2[NN * 4];    // .w accumulates denominator
__device__ int   g_src[NE];                       // edge indices, normalized to int32
__device__ int   g_dst[NE];
__device__ int   g_is64;

__device__ __forceinline__ float lrelu(float x) { return x > 0.f ? x : 0.2f * x; }

// Vector atomic adds via official intrinsics (sm_90+).
__device__ __forceinline__ void atomic_add4(float* p, float a, float b, float c, float d) {
    atomicAdd((float4*)p, make_float4(a, b, c, d));
}
__device__ __forceinline__ void atomic_add2(float* p, float a, float b) {
    atomicAdd((float2*)p, make_float2(a, b));
}

// ---------------- dtype sniff: is edge_index stored as int64 or int32? ----------------
// If int64 (little-endian, values in [0, 50000)), every odd int32 word is 0.
// If int32, odd words are random edge indices — all-zero is ~impossible.
__global__ void detect_kernel(const unsigned* __restrict__ w) {
    if (threadIdx.x == 0 && blockIdx.x == 0) {
        int nz = 0;
#pragma unroll 4
        for (int i = 0; i < 128; i++) nz += (w[2 * i + 1] != 0u);
        g_is64 = (nz == 0) ? 1 : 0;
    }
}

// ---------------- normalize edge indices to int32 (clamped defensively) ----------------
__global__ void convert_kernel(const void* __restrict__ ei) {
    int e = blockIdx.x * blockDim.x + threadIdx.x;
    if (e >= NE) return;
    int s, d;
    if (g_is64) {
        const long long* p = (const long long*)ei;
        s = (int)p[e];
        d = (int)p[NE + e];
    } else {
        const int* p = (const int*)ei;
        s = p[e];
        d = p[NE + e];
    }
    s = min(max(s, 0), NN - 1);
    d = min(max(d, 0), NN - 1);
    g_src[e] = s;
    g_dst[e] = d;
}

// ---------------- zero accumulators (graph-capturable) ----------------
__global__ void zero_kernel() {
    int64_t i = (int64_t)blockIdx.x * blockDim.x + threadIdx.x;
    int64_t stride = (int64_t)gridDim.x * blockDim.x;
    const int64_t n_out1 = (int64_t)NN * F1 / 4;       // float4 count
    for (int64_t k = i; k < n_out1; k += stride)
        ((float4*)g_out1)[k] = make_float4(0.f, 0.f, 0.f, 0.f);
    for (int64_t k = i; k < NN; k += stride) {
        ((float2*)g_den1)[k] = make_float2(0.f, 0.f);
        ((float4*)g_out2)[k] = make_float4(0.f, 0.f, 0.f, 0.f);
    }
}

// ---------------- GEMM1: g_h1 = x[NN,256] @ W1[256,256] ----------------
// 64x64 tile, BK=16, 256 threads, 4x4 microtile.
__global__ void gemm1_kernel(const float* __restrict__ A, const float* __restrict__ B) {
    __shared__ float As[16][64];
    __shared__ float Bs[16][64];
    const int m0 = blockIdx.x * 64;
    const int n0 = blockIdx.y * 64;
    const int t  = threadIdx.x;
    const int tx = t & 15, ty = t >> 4;

    const int arow = t >> 2, aq = t & 3;   // A tile: 64 rows x 16 cols
    const int brow = t >> 4, bq = t & 15;  // B tile: 16 rows x 64 cols

    float acc[4][4] = {};

    for (int k0 = 0; k0 < INC; k0 += 16) {
        float4 av = make_float4(0.f, 0.f, 0.f, 0.f);
        int ar = m0 + arow;
        if (ar < NN) av = *(const float4*)(A + (size_t)ar * INC + k0 + aq * 4);
        As[aq * 4 + 0][arow] = av.x;
        As[aq * 4 + 1][arow] = av.y;
        As[aq * 4 + 2][arow] = av.z;
        As[aq * 4 + 3][arow] = av.w;

        float4 bv = *(const float4*)(B + (size_t)(k0 + brow) * F1 + n0 + bq * 4);
        *(float4*)&Bs[brow][bq * 4] = bv;
        __syncthreads();

#pragma unroll
        for (int k = 0; k < 16; k++) {
            float a[4], b[4];
#pragma unroll
            for (int i = 0; i < 4; i++) a[i] = As[k][ty * 4 + i];
#pragma unroll
            for (int j = 0; j < 4; j++) b[j] = Bs[k][tx * 4 + j];
#pragma unroll
            for (int i = 0; i < 4; i++)
#pragma unroll
                for (int j = 0; j < 4; j++) acc[i][j] = fmaf(a[i], b[j], acc[i][j]);
        }
        __syncthreads();
    }

#pragma unroll
    for (int i = 0; i < 4; i++) {
        int row = m0 + ty * 4 + i;
        if (row < NN) {
            float4 v = make_float4(acc[i][0], acc[i][1], acc[i][2], acc[i][3]);
            *(float4*)(g_h1 + (size_t)row * F1 + n0 + tx * 4) = v;
        }
    }
}

// ---------------- per-node attention logits for layer 1 ----------------
// warp per node; lanes 0-15 = head 0, lanes 16-31 = head 1.
__global__ void att1_kernel(const float* __restrict__ a_src, const float* __restrict__ a_dst) {
    int n = blockIdx.x * 8 + (threadIdx.x >> 5);
    int lane = threadIdx.x & 31;
    if (n >= NN) return;

    const float4* hp = (const float4*)(g_h1 + (size_t)n * F1);
    float4 h0 = hp[lane * 2], h1 = hp[lane * 2 + 1];
    const float4* sp = (const float4*)a_src;
    float4 s0 = sp[lane * 2], s1 = sp[lane * 2 + 1];
    const float4* dp = (const float4*)a_dst;
    float4 d0 = dp[lane * 2], d1 = dp[lane * 2 + 1];

    float ss = h0.x * s0.x + h0.y * s0.y + h0.z * s0.z + h0.w * s0.w
             + h1.x * s1.x + h1.y * s1.y + h1.z * s1.z + h1.w * s1.w;
    float sd = h0.x * d0.x + h0.y * d0.y + h0.z * d0.z + h0.w * d0.w
             + h1.x * d1.x + h1.y * d1.y + h1.z * d1.z + h1.w * d1.w;

#pragma unroll
    for (int off = 8; off; off >>= 1) {
        ss += __shfl_xor_sync(0xffffffffu, ss, off);
        sd += __shfl_xor_sync(0xffffffffu, sd, off);
    }
    if ((lane & 15) == 0) {
        int h = lane >> 4;
        g_als1[n * 2 + h] = ss;
        g_ald1[n * 2 + h] = sd;
    }
}

// ---------------- layer-1 edge pass: unnormalized softmax aggregation ----------------
// warp per edge. w = exp(leaky(als[src]+ald[dst])); den[dst]+=w; out1[dst]+=w*h1[src].
__global__ void edge1_kernel() {
    int e = blockIdx.x * 8 + (threadIdx.x >> 5);
    int lane = threadIdx.x & 31;
    if (e >= NE) return;

    int s = g_src[e];
    int d = g_dst[e];

    float2 as = *(const float2*)(g_als1 + 2 * s);
    float2 ad = *(const float2*)(g_ald1 + 2 * d);
    float w0 = __expf(lrelu(as.x + ad.x));
    float w1 = __expf(lrelu(as.y + ad.y));

    if (lane == 0) {
        atomic_add2(g_den1 + 2 * d, w0, w1);
    }

    float w = (lane < 16) ? w0 : w1;
    const float4* hp = (const float4*)(g_h1 + (size_t)s * F1);
    float4 u = hp[lane * 2], v = hp[lane * 2 + 1];
    float* op = g_out1 + (size_t)d * F1 + lane * 8;
    atomic_add4(op,     u.x * w, u.y * w, u.z * w, u.w * w);
    atomic_add4(op + 4, v.x * w, v.y * w, v.z * w, v.w * w);
}

// ---------------- fused: layer1 normalize+bias+ELU -> GEMM2 -> layer2 logits ----------------
// warp per node.
__global__ void node1_kernel(const float* __restrict__ b1, const float* __restrict__ W2,
                             const float* __restrict__ as2, const float* __restrict__ ad2) {
    int n = blockIdx.x * 8 + (threadIdx.x >> 5);
    int lane = threadIdx.x & 31;
    if (n >= NN) return;

    int h = lane >> 4;
    float inv = 1.0f / fmaxf(g_den1[n * 2 + h], 1e-16f);

    const float4* op = (const float4*)(g_out1 + (size_t)n * F1);
    float4 u = op[lane * 2], v = op[lane * 2 + 1];
    const float4* bp = (const float4*)b1;
    float4 bu = bp[lane * 2], bv = bp[lane * 2 + 1];

    float f[8];
    f[0] = u.x * inv + bu.x; f[1] = u.y * inv + bu.y;
    f[2] = u.z * inv + bu.z; f[3] = u.w * inv + bu.w;
    f[4] = v.x * inv + bv.x; f[5] = v.y * inv + bv.y;
    f[6] = v.z * inv + bv.z; f[7] = v.w * inv + bv.w;
#pragma unroll
    for (int j = 0; j < 8; j++) f[j] = f[j] > 0.f ? f[j] : (__expf(f[j]) - 1.0f);

    float a0 = 0.f, a1 = 0.f, a2 = 0.f;
    int kbase = lane * 8;
#pragma unroll
    for (int j = 0; j < 8; j++) {
        const float* w = W2 + (size_t)(kbase + j) * OC;
        a0 = fmaf(f[j], w[0], a0);
        a1 = fmaf(f[j], w[1], a1);
        a2 = fmaf(f[j], w[2], a2);
    }
#pragma unroll
    for (int off = 16; off; off >>= 1) {
        a0 += __shfl_xor_sync(0xffffffffu, a0, off);
        a1 += __shfl_xor_sync(0xffffffffu, a1, off);
        a2 += __shfl_xor_sync(0xffffffffu, a2, off);
    }
    if (lane == 0) {
        *(float4*)(g_h2 + (size_t)n * 4) = make_float4(a0, a1, a2, 1.0f);
        g_als2[n] = a0 * as2[0] + a1 * as2[1] + a2 * as2[2];
        g_ald2[n] = a0 * ad2[0] + a1 * ad2[1] + a2 * ad2[2];
    }
}

// ---------------- layer-2 edge pass ----------------
// h2.w = 1, so out2.w accumulates the softmax denominator for free.
__global__ void edge2_kernel() {
    int e = blockIdx.x * blockDim.x + threadIdx.x;
    if (e >= NE) return;
    int s = g_src[e];
    int d = g_dst[e];
    float w = __expf(lrelu(g_als2[s] + g_ald2[d]));
    float4 hv = *(const float4*)(g_h2 + (size_t)s * 4);
    atomic_add4(g_out2 + (size_t)d * 4, hv.x * w, hv.y * w, hv.z * w, w);
}

// ---------------- final: normalize + bias + log_softmax ----------------
__global__ void node2_kernel(const float* __restrict__ b2, float* __restrict__ out) {
    int n = blockIdx.x * blockDim.x + threadIdx.x;
    if (n >= NN) return;
    float4 o4 = *(const float4*)(g_out2 + (size_t)n * 4);
    float inv = 1.0f / fmaxf(o4.w, 1e-16f);
    float o0 = o4.x * inv + b2[0];
    float o1 = o4.y * inv + b2[1];
    float o2 = o4.z * inv + b2[2];
    float m = fmaxf(o0, fmaxf(o1, o2));
    float l = logf(expf(o0 - m) + expf(o1 - m) + expf(o2 - m)) + m;
    out[n * 3 + 0] = o0 - l;
    out[n * 3 + 1] = o1 - l;
    out[n * 3 + 2] = o2 - l;
}

extern "C" void kernel_launch(void* const* d_in, const int* in_sizes, int n_in,
                              void* d_out, int out_size) {
    const float* x   = (const float*)d_in[0];
    const void*  ei  = d_in[1];
    const float* W1  = (const float*)d_in[2];
    const float* as1 = (const float*)d_in[3];
    const float* ad1 = (const float*)d_in[4];
    const float* b1  = (const float*)d_in[5];
    const float* W2  = (const float*)d_in[6];
    const float* as2 = (const float*)d_in[7];
    const float* ad2 = (const float*)d_in[8];
    const float* b2  = (const float*)d_in[9];

    detect_kernel<<<1, 32>>>((const unsigned*)ei);
    convert_kernel<<<(NE + 255) / 256, 256>>>(ei);
    zero_kernel<<<592, 256>>>();

    gemm1_kernel<<<dim3((NN + 63) / 64, F1 / 64), 256>>>(x, W1);
    att1_kernel<<<(NN + 7) / 8, 256>>>(as1, ad1);
    edge1_kernel<<<(NE + 7) / 8, 256>>>();
    node1_kernel<<<(NN + 7) / 8, 256>>>(b1, W2, as2, ad2);
    edge2_kernel<<<(NE + 255) / 256, 256>>>();
    node2_kernel<<<(NN + 255) / 256, 256>>>(b2, (float*)d_out);
}

// round 16
// speedup vs baseline: 1.4049x; 1.4049x over previous
#include <cuda_runtime.h>
#include <cstdint>

#define NN   50000
#define NE   1000000
#define INC  256
#define F1   256   // HEADS * HID_CH
#define OC   3

// ---------------- scratch (device globals; no allocation allowed) ----------------
__device__ __align__(16) float g_h1[NN * F1];     // layer1 features h = x@W1
__device__ __align__(8)  float g_als1[NN * 2];
__device__ __align__(8)  float g_ald1[NN * 2];
__device__ __align__(16) float g_h2[NN * 4];      // layer2 features (padded)
__device__ float g_als2[NN];
__device__ float g_ald2[NN];
__device__ int   g_src[NE];                       // edge indices, normalized int32
__device__ int   g_dst[NE];
__device__ int   g_esrc[NE];                      // src indices sorted by dst (CSR)
__device__ int   g_cnt[NN];                       // histogram, then scatter cursor
__device__ int   g_off[NN + 1];                   // CSR offsets
__device__ int   g_is64;

__device__ __forceinline__ float lrelu(float x) { return x > 0.f ? x : 0.2f * x; }

// ---------------- dtype sniff: int64 vs int32 edge_index ----------------
__global__ void detect_kernel(const unsigned* __restrict__ w) {
    if (threadIdx.x == 0 && blockIdx.x == 0) {
        int nz = 0;
#pragma unroll 4
        for (int i = 0; i < 128; i++) nz += (w[2 * i + 1] != 0u);
        g_is64 = (nz == 0) ? 1 : 0;
    }
}

__global__ void zero_cnt_kernel() {
    int i = blockIdx.x * blockDim.x + threadIdx.x;
    if (i < NN) g_cnt[i] = 0;
}

// ---------------- normalize indices to int32 (clamped) + dst histogram ----------------
__global__ void convert_kernel(const void* __restrict__ ei) {
    int e = blockIdx.x * blockDim.x + threadIdx.x;
    if (e >= NE) return;
    int s, d;
    if (g_is64) {
        const long long* p = (const long long*)ei;
        s = (int)p[e];
        d = (int)p[NE + e];
    } else {
        const int* p = (const int*)ei;
        s = p[e];
        d = p[NE + e];
    }
    s = min(max(s, 0), NN - 1);
    d = min(max(d, 0), NN - 1);
    g_src[e] = s;
    g_dst[e] = d;
    atomicAdd(&g_cnt[d], 1);
}

// ---------------- exclusive scan of g_cnt -> g_off (single block) ----------------
__global__ void scan_kernel() {
    __shared__ int carry;
    __shared__ int buf[1024];
    const int t = threadIdx.x;
    if (t == 0) carry = 0;
    __syncthreads();
    for (int base = 0; base < NN; base += 1024) {
        int i = base + t;
        int v = (i < NN) ? g_cnt[i] : 0;
        buf[t] = v;
        __syncthreads();
        for (int s = 1; s < 1024; s <<= 1) {
            int tv = (t >= s) ? buf[t - s] : 0;
            __syncthreads();
            buf[t] += tv;
            __syncthreads();
        }
        int incl = buf[t] + carry;
        if (i < NN) { g_off[i] = incl - v; g_cnt[i] = incl - v; }  // cursor = offset
        __syncthreads();
        if (t == 1023) carry = incl;
        __syncthreads();
    }
    if (t == 0) g_off[NN] = carry;
}

// ---------------- scatter: edges sorted by dst (order within dst arbitrary) ----------------
__global__ void scatter_kernel() {
    int e = blockIdx.x * blockDim.x + threadIdx.x;
    if (e >= NE) return;
    int d = g_dst[e];
    int pos = atomicAdd(&g_cnt[d], 1);
    g_esrc[pos] = g_src[e];
}

// ---------------- GEMM1: g_h1 = x[NN,256] @ W1[256,256] ----------------
// 128x128 tile, BK=16, 256 threads, 8x8 microtile (halves LDS per FMA vs 4x4).
__global__ void gemm1_kernel(const float* __restrict__ A, const float* __restrict__ B) {
    __shared__ float As[16][132];
    __shared__ float Bs[16][132];
    const int m0 = blockIdx.x * 128;
    const int n0 = blockIdx.y * 128;
    const int t  = threadIdx.x;
    const int tx = t & 15, ty = t >> 4;

    float acc[8][8] = {};

    for (int k0 = 0; k0 < INC; k0 += 16) {
#pragma unroll
        for (int l = 0; l < 2; l++) {
            int idx = t + l * 256;
            int row = idx >> 2, q = idx & 3;       // A: 128 rows x 16 cols
            float4 av = make_float4(0.f, 0.f, 0.f, 0.f);
            int ar = m0 + row;
            if (ar < NN) av = *(const float4*)(A + (size_t)ar * INC + k0 + q * 4);
            As[q * 4 + 0][row] = av.x;
            As[q * 4 + 1][row] = av.y;
            As[q * 4 + 2][row] = av.z;
            As[q * 4 + 3][row] = av.w;
            int kr = idx >> 5, c4 = idx & 31;      // B: 16 rows x 128 cols
            float4 bv = *(const float4*)(B + (size_t)(k0 + kr) * F1 + n0 + c4 * 4);
            *(float4*)&Bs[kr][c4 * 4] = bv;
        }
        __syncthreads();

#pragma unroll
        for (int k = 0; k < 16; k++) {
            float a[8], b[8];
            *(float4*)&a[0] = *(float4*)&As[k][ty * 8];
            *(float4*)&a[4] = *(float4*)&As[k][ty * 8 + 4];
            *(float4*)&b[0] = *(float4*)&Bs[k][tx * 8];
            *(float4*)&b[4] = *(float4*)&Bs[k][tx * 8 + 4];
#pragma unroll
            for (int i = 0; i < 8; i++)
#pragma unroll
                for (int j = 0; j < 8; j++) acc[i][j] = fmaf(a[i], b[j], acc[i][j]);
        }
        __syncthreads();
    }

#pragma unroll
    for (int i = 0; i < 8; i++) {
        int row = m0 + ty * 8 + i;
        if (row < NN) {
            *(float4*)(g_h1 + (size_t)row * F1 + n0 + tx * 8) =
                make_float4(acc[i][0], acc[i][1], acc[i][2], acc[i][3]);
            *(float4*)(g_h1 + (size_t)row * F1 + n0 + tx * 8 + 4) =
                make_float4(acc[i][4], acc[i][5], acc[i][6], acc[i][7]);
        }
    }
}

// ---------------- per-node attention logits for layer 1 ----------------
__global__ void att1_kernel(const float* __restrict__ a_src, const float* __restrict__ a_dst) {
    int n = blockIdx.x * 8 + (threadIdx.x >> 5);
    int lane = threadIdx.x & 31;
    if (n >= NN) return;

    const float4* hp = (const float4*)(g_h1 + (size_t)n * F1);
    float4 h0 = hp[lane * 2], h1 = hp[lane * 2 + 1];
    const float4* sp = (const float4*)a_src;
    float4 s0 = sp[lane * 2], s1 = sp[lane * 2 + 1];
    const float4* dp = (const float4*)a_dst;
    float4 d0 = dp[lane * 2], d1 = dp[lane * 2 + 1];

    float ss = h0.x * s0.x + h0.y * s0.y + h0.z * s0.z + h0.w * s0.w
             + h1.x * s1.x + h1.y * s1.y + h1.z * s1.z + h1.w * s1.w;
    float sd = h0.x * d0.x + h0.y * d0.y + h0.z * d0.z + h0.w * d0.w
             + h1.x * d1.x + h1.y * d1.y + h1.z * d1.z + h1.w * d1.w;

#pragma unroll
    for (int off = 8; off; off >>= 1) {
        ss += __shfl_xor_sync(0xffffffffu, ss, off);
        sd += __shfl_xor_sync(0xffffffffu, sd, off);
    }
    if ((lane & 15) == 0) {
        int h = lane >> 4;
        g_als1[n * 2 + h] = ss;
        g_ald1[n * 2 + h] = sd;
    }
}

// ---------------- layer-1 aggregation over CSR + fused epilogue ----------------
// Warp per dst node. Register accumulation (no atomics, no g_out1), then
// normalize+bias+ELU -> GEMM2 (256->3) -> layer-2 attention logits.
__global__ void agg1_kernel(const float* __restrict__ b1, const float* __restrict__ W2,
                            const float* __restrict__ as2, const float* __restrict__ ad2) {
    int n = blockIdx.x * 8 + (threadIdx.x >> 5);
    int lane = threadIdx.x & 31;
    if (n >= NN) return;

    int beg = g_off[n], end = g_off[n + 1];
    float2 ad = *(const float2*)(g_ald1 + 2 * n);

    float acc[8] = {};
    float wsum = 0.f;

    for (int base = beg; base < end; base += 32) {
        int idx = base + lane;
        int s = 0;
        float w0 = 0.f, w1 = 0.f;
        if (idx < end) {
            s = g_esrc[idx];
            float2 as = *(const float2*)(g_als1 + 2 * s);
            w0 = __expf(lrelu(as.x + ad.x));
            w1 = __expf(lrelu(as.y + ad.y));
        }
        int cnt = min(end - base, 32);
        for (int j = 0; j < cnt; j++) {
            int   sj  = __shfl_sync(0xffffffffu, s,  j);
            float w0j = __shfl_sync(0xffffffffu, w0, j);
            float w1j = __shfl_sync(0xffffffffu, w1, j);
            float wj = (lane < 16) ? w0j : w1j;
            const float4* hp = (const float4*)(g_h1 + (size_t)sj * F1) + lane * 2;
            float4 u = hp[0], v = hp[1];
            acc[0] = fmaf(u.x, wj, acc[0]);
            acc[1] = fmaf(u.y, wj, acc[1]);
            acc[2] = fmaf(u.z, wj, acc[2]);
            acc[3] = fmaf(u.w, wj, acc[3]);
            acc[4] = fmaf(v.x, wj, acc[4]);
            acc[5] = fmaf(v.y, wj, acc[5]);
            acc[6] = fmaf(v.z, wj, acc[6]);
            acc[7] = fmaf(v.w, wj, acc[7]);
            wsum += wj;
        }
    }

    // epilogue: normalize + bias + ELU, GEMM2, layer-2 logits
    float inv = 1.0f / fmaxf(wsum, 1e-16f);
    const float4* bp = (const float4*)b1;
    float4 bu = bp[lane * 2], bv = bp[lane * 2 + 1];

    float f[8];
    f[0] = acc[0] * inv + bu.x; f[1] = acc[1] * inv + bu.y;
    f[2] = acc[2] * inv + bu.z; f[3] = acc[3] * inv + bu.w;
    f[4] = acc[4] * inv + bv.x; f[5] = acc[5] * inv + bv.y;
    f[6] = acc[6] * inv + bv.z; f[7] = acc[7] * inv + bv.w;
#pragma unroll
    for (int j = 0; j < 8; j++) f[j] = f[j] > 0.f ? f[j] : (__expf(f[j]) - 1.0f);

    float a0 = 0.f, a1 = 0.f, a2 = 0.f;
    int kbase = lane * 8;
#pragma unroll
    for (int j = 0; j < 8; j++) {
        const float* w = W2 + (size_t)(kbase + j) * OC;
        a0 = fmaf(f[j], w[0], a0);
        a1 = fmaf(f[j], w[1], a1);
        a2 = fmaf(f[j], w[2], a2);
    }
#pragma unroll
    for (int off = 16; off; off >>= 1) {
        a0 += __shfl_xor_sync(0xffffffffu, a0, off);
        a1 += __shfl_xor_sync(0xffffffffu, a1, off);
        a2 += __shfl_xor_sync(0xffffffffu, a2, off);
    }
    if (lane == 0) {
        *(float4*)(g_h2 + (size_t)n * 4) = make_float4(a0, a1, a2, 0.f);
        g_als2[n] = a0 * as2[0] + a1 * as2[1] + a2 * as2[2];
        g_ald2[n] = a0 * ad2[0] + a1 * ad2[1] + a2 * ad2[2];
    }
}

// ---------------- layer-2 aggregation (thread per node) + log_softmax ----------------
__global__ void agg2_kernel(const float* __restrict__ b2, float* __restrict__ out) {
    int n = blockIdx.x * blockDim.x + threadIdx.x;
    if (n >= NN) return;
    int beg = g_off[n], end = g_off[n + 1];
    float ald = g_ald2[n];
    float a0 = 0.f, a1 = 0.f, a2 = 0.f, den = 0.f;
    for (int i = beg; i < end; i++) {
        int s = g_esrc[i];
        float w = __expf(lrelu(g_als2[s] + ald));
        float4 hv = *(const float4*)(g_h2 + (size_t)s * 4);
        a0 = fmaf(hv.x, w, a0);
        a1 = fmaf(hv.y, w, a1);
        a2 = fmaf(hv.z, w, a2);
        den += w;
    }
    float inv = 1.0f / fmaxf(den, 1e-16f);
    float o0 = a0 * inv + b2[0];
    float o1 = a1 * inv + b2[1];
    float o2 = a2 * inv + b2[2];
    float m = fmaxf(o0, fmaxf(o1, o2));
    float l = logf(expf(o0 - m) + expf(o1 - m) + expf(o2 - m)) + m;
    out[n * 3 + 0] = o0 - l;
    out[n * 3 + 1] = o1 - l;
    out[n * 3 + 2] = o2 - l;
}

extern "C" void kernel_launch(void* const* d_in, const int* in_sizes, int n_in,
                              void* d_out, int out_size) {
    const float* x   = (const float*)d_in[0];
    const void*  ei  = d_in[1];
    const float* W1  = (const float*)d_in[2];
    const float* as1 = (const float*)d_in[3];
    const float* ad1 = (const float*)d_in[4];
    const float* b1  = (const float*)d_in[5];
    const float* W2  = (const float*)d_in[6];
    const float* as2 = (const float*)d_in[7];
    const float* ad2 = (const float*)d_in[8];
    const float* b2  = (const float*)d_in[9];

    zero_cnt_kernel<<<(NN + 255) / 256, 256>>>();
    detect_kernel<<<1, 32>>>((const unsigned*)ei);
    convert_kernel<<<(NE + 255) / 256, 256>>>(ei);
    scan_kernel<<<1, 1024>>>();
    scatter_kernel<<<(NE + 255) / 256, 256>>>();

    gemm1_kernel<<<dim3((NN + 127) / 128, F1 / 128), 256>>>(x, W1);
    att1_kernel<<<(NN + 7) / 8, 256>>>(as1, ad1);
    agg1_kernel<<<(NN + 7) / 8, 256>>>(b1, W2, as2, ad2);
    agg2_kernel<<<(NN + 255) / 256, 256>>>(b2, (float*)d_out);
}

// round 17
// speedup vs baseline: 1.6409x; 1.1680x over previous
#include <cuda_runtime.h>
#include <cstdint>

#define NN   50000
#define NE   1000000
#define INC  256
#define F1   256   // HEADS * HID_CH
#define OC   3
#define SCAN_NB ((NN + 1023) / 1024)   // 49 blocks

// ---------------- scratch (device globals; no allocation allowed) ----------------
__device__ __align__(16) float g_h1[NN * F1];     // layer1 features h = x@W1
__device__ __align__(8)  float g_als1[NN * 2];
__device__ __align__(8)  float g_ald1[NN * 2];
__device__ __align__(16) float g_h2[NN * 4];      // layer2 features (padded)
__device__ float g_als2[NN];
__device__ float g_ald2[NN];
__device__ int   g_src[NE];                       // edge indices, normalized int32
__device__ int   g_dst[NE];
__device__ int   g_esrc[NE];                      // src indices sorted by dst (CSR)
__device__ int   g_cnt[NN];                       // histogram, then scatter cursor
__device__ int   g_off[NN + 1];                   // CSR offsets
__device__ int   g_bsum[SCAN_NB];                 // per-block scan totals
__device__ int   g_boff[SCAN_NB];                 // exclusive block offsets
__device__ int   g_is64;

__device__ __forceinline__ float lrelu(float x) { return x > 0.f ? x : 0.2f * x; }

// ---------------- dtype sniff: int64 vs int32 edge_index ----------------
__global__ void detect_kernel(const unsigned* __restrict__ w) {
    if (threadIdx.x == 0 && blockIdx.x == 0) {
        int nz = 0;
#pragma unroll 4
        for (int i = 0; i < 128; i++) nz += (w[2 * i + 1] != 0u);
        g_is64 = (nz == 0) ? 1 : 0;
    }
}

__global__ void zero_cnt_kernel() {
    int i = blockIdx.x * blockDim.x + threadIdx.x;
    if (i < NN) g_cnt[i] = 0;
}

// ---------------- normalize indices to int32 (clamped) + dst histogram ----------------
__global__ void convert_kernel(const void* __restrict__ ei) {
    int e = blockIdx.x * blockDim.x + threadIdx.x;
    if (e >= NE) return;
    int s, d;
    if (g_is64) {
        const long long* p = (const long long*)ei;
        s = (int)p[e];
        d = (int)p[NE + e];
    } else {
        const int* p = (const int*)ei;
        s = p[e];
        d = p[NE + e];
    }
    s = min(max(s, 0), NN - 1);
    d = min(max(d, 0), NN - 1);
    g_src[e] = s;
    g_dst[e] = d;
    atomicAdd(&g_cnt[d], 1);
}

// ---------------- multi-block exclusive scan of g_cnt -> g_off ----------------
// Phase 1: per-block local scan (warp shuffles), emit block sums.
__global__ void scan1_kernel() {
    __shared__ int warp_sums[32];
    const int t = threadIdx.x;
    const int lane = t & 31, wid = t >> 5;
    int i = blockIdx.x * 1024 + t;
    int v = (i < NN) ? g_cnt[i] : 0;

    int x = v;
#pragma unroll
    for (int off = 1; off < 32; off <<= 1) {
        int y = __shfl_up_sync(0xffffffffu, x, off);
        if (lane >= off) x += y;
    }
    if (lane == 31) warp_sums[wid] = x;
    __syncthreads();
    if (wid == 0) {
        int s = warp_sums[lane];
#pragma unroll
        for (int off = 1; off < 32; off <<= 1) {
            int y = __shfl_up_sync(0xffffffffu, s, off);
            if (lane >= off) s += y;
        }
        warp_sums[lane] = s;
    }
    __syncthreads();
    int base = (wid > 0) ? warp_sums[wid - 1] : 0;
    int incl = x + base;
    if (i < NN) g_off[i] = incl - v;          // block-local exclusive
    if (t == 1023) g_bsum[blockIdx.x] = incl; // block total
}

// Phase 2: scan the 49 block sums (one warp, shuffle scan over padded 64).
__global__ void scan2_kernel() {
    const int lane = threadIdx.x;   // 64 threads
    int v = (lane < SCAN_NB) ? g_bsum[lane] : 0;
    int x = v;
#pragma unroll
    for (int off = 1; off < 32; off <<= 1) {
        int y = __shfl_up_sync(0xffffffffu, x, off);
        if ((lane & 31) >= off) x += y;
    }
    __shared__ int w0_total;
    if (lane == 31) w0_total = x;
    __syncthreads();
    int incl = (lane < 32) ? x : x + w0_total;
    if (lane < SCAN_NB) g_boff[lane] = incl - v;
    if (lane == SCAN_NB - 1) g_off[NN] = incl;  // grand total = NE
}

// Phase 3: add block offsets; materialize scatter cursor.
__global__ void scan3_kernel() {
    int i = blockIdx.x * 1024 + threadIdx.x;
    if (i >= NN) return;
    int o = g_off[i] + g_boff[blockIdx.x];
    g_off[i] = o;
    g_cnt[i] = o;
}

// ---------------- scatter: edges sorted by dst (order within dst arbitrary) ----------------
__global__ void scatter_kernel() {
    int e = blockIdx.x * blockDim.x + threadIdx.x;
    if (e >= NE) return;
    int d = g_dst[e];
    int pos = atomicAdd(&g_cnt[d], 1);
    g_esrc[pos] = g_src[e];
}

// ---------------- GEMM1: g_h1 = x[NN,256] @ W1[256,256] ----------------
// 128x128 tile, BK=16, 256 threads, 8x8 microtile.
__global__ void gemm1_kernel(const float* __restrict__ A, const float* __restrict__ B) {
    __shared__ float As[16][132];
    __shared__ float Bs[16][132];
    const int m0 = blockIdx.x * 128;
    const int n0 = blockIdx.y * 128;
    const int t  = threadIdx.x;
    const int tx = t & 15, ty = t >> 4;

    float acc[8][8] = {};

    for (int k0 = 0; k0 < INC; k0 += 16) {
#pragma unroll
        for (int l = 0; l < 2; l++) {
            int idx = t + l * 256;
            int row = idx >> 2, q = idx & 3;       // A: 128 rows x 16 cols
            float4 av = make_float4(0.f, 0.f, 0.f, 0.f);
            int ar = m0 + row;
            if (ar < NN) av = *(const float4*)(A + (size_t)ar * INC + k0 + q * 4);
            As[q * 4 + 0][row] = av.x;
            As[q * 4 + 1][row] = av.y;
            As[q * 4 + 2][row] = av.z;
            As[q * 4 + 3][row] = av.w;
            int kr = idx >> 5, c4 = idx & 31;      // B: 16 rows x 128 cols
            float4 bv = *(const float4*)(B + (size_t)(k0 + kr) * F1 + n0 + c4 * 4);
            *(float4*)&Bs[kr][c4 * 4] = bv;
        }
        __syncthreads();

#pragma unroll
        for (int k = 0; k < 16; k++) {
            float a[8], b[8];
            *(float4*)&a[0] = *(float4*)&As[k][ty * 8];
            *(float4*)&a[4] = *(float4*)&As[k][ty * 8 + 4];
            *(float4*)&b[0] = *(float4*)&Bs[k][tx * 8];
            *(float4*)&b[4] = *(float4*)&Bs[k][tx * 8 + 4];
#pragma unroll
            for (int i = 0; i < 8; i++)
#pragma unroll
                for (int j = 0; j < 8; j++) acc[i][j] = fmaf(a[i], b[j], acc[i][j]);
        }
        __syncthreads();
    }

#pragma unroll
    for (int i = 0; i < 8; i++) {
        int row = m0 + ty * 8 + i;
        if (row < NN) {
            *(float4*)(g_h1 + (size_t)row * F1 + n0 + tx * 8) =
                make_float4(acc[i][0], acc[i][1], acc[i][2], acc[i][3]);
            *(float4*)(g_h1 + (size_t)row * F1 + n0 + tx * 8 + 4) =
                make_float4(acc[i][4], acc[i][5], acc[i][6], acc[i][7]);
        }
    }
}

// ---------------- per-node attention logits for layer 1 ----------------
__global__ void att1_kernel(const float* __restrict__ a_src, const float* __restrict__ a_dst) {
    int n = blockIdx.x * 8 + (threadIdx.x >> 5);
    int lane = threadIdx.x & 31;
    if (n >= NN) return;

    const float4* hp = (const float4*)(g_h1 + (size_t)n * F1);
    float4 h0 = hp[lane * 2], h1 = hp[lane * 2 + 1];
    const float4* sp = (const float4*)a_src;
    float4 s0 = sp[lane * 2], s1 = sp[lane * 2 + 1];
    const float4* dp = (const float4*)a_dst;
    float4 d0 = dp[lane * 2], d1 = dp[lane * 2 + 1];

    float ss = h0.x * s0.x + h0.y * s0.y + h0.z * s0.z + h0.w * s0.w
             + h1.x * s1.x + h1.y * s1.y + h1.z * s1.z + h1.w * s1.w;
    float sd = h0.x * d0.x + h0.y * d0.y + h0.z * d0.z + h0.w * d0.w
             + h1.x * d1.x + h1.y * d1.y + h1.z * d1.z + h1.w * d1.w;

#pragma unroll
    for (int off = 8; off; off >>= 1) {
        ss += __shfl_xor_sync(0xffffffffu, ss, off);
        sd += __shfl_xor_sync(0xffffffffu, sd, off);
    }
    if ((lane & 15) == 0) {
        int h = lane >> 4;
        g_als1[n * 2 + h] = ss;
        g_ald1[n * 2 + h] = sd;
    }
}

// ---------------- layer-1 aggregation over CSR + fused epilogue ----------------
// Warp per dst node; register accumulation, then normalize+bias+ELU -> GEMM2 -> logits.
__global__ void agg1_kernel(const float* __restrict__ b1, const float* __restrict__ W2,
                            const float* __restrict__ as2, const float* __restrict__ ad2) {
    int n = blockIdx.x * 8 + (threadIdx.x >> 5);
    int lane = threadIdx.x & 31;
    if (n >= NN) return;

    int beg = g_off[n], end = g_off[n + 1];
    float2 ad = *(const float2*)(g_ald1 + 2 * n);

    float acc[8] = {};
    float wsum = 0.f;

    for (int base = beg; base < end; base += 32) {
        int idx = base + lane;
        int s = 0;
        float w0 = 0.f, w1 = 0.f;
        if (idx < end) {
            s = g_esrc[idx];
            float2 as = *(const float2*)(g_als1 + 2 * s);
            w0 = __expf(lrelu(as.x + ad.x));
            w1 = __expf(lrelu(as.y + ad.y));
        }
        int cnt = min(end - base, 32);
        for (int j = 0; j < cnt; j++) {
            int   sj  = __shfl_sync(0xffffffffu, s,  j);
            float w0j = __shfl_sync(0xffffffffu, w0, j);
            float w1j = __shfl_sync(0xffffffffu, w1, j);
            float wj = (lane < 16) ? w0j : w1j;
            const float4* hp = (const float4*)(g_h1 + (size_t)sj * F1) + lane * 2;
            float4 u = hp[0], v = hp[1];
            acc[0] = fmaf(u.x, wj, acc[0]);
            acc[1] = fmaf(u.y, wj, acc[1]);
            acc[2] = fmaf(u.z, wj, acc[2]);
            acc[3] = fmaf(u.w, wj, acc[3]);
            acc[4] = fmaf(v.x, wj, acc[4]);
            acc[5] = fmaf(v.y, wj, acc[5]);
            acc[6] = fmaf(v.z, wj, acc[6]);
            acc[7] = fmaf(v.w, wj, acc[7]);
            wsum += wj;
        }
    }

    float inv = 1.0f / fmaxf(wsum, 1e-16f);
    const float4* bp = (const float4*)b1;
    float4 bu = bp[lane * 2], bv = bp[lane * 2 + 1];

    float f[8];
    f[0] = acc[0] * inv + bu.x; f[1] = acc[1] * inv + bu.y;
    f[2] = acc[2] * inv + bu.z; f[3] = acc[3] * inv + bu.w;
    f[4] = acc[4] * inv + bv.x; f[5] = acc[5] * inv + bv.y;
    f[6] = acc[6] * inv + bv.z; f[7] = acc[7] * inv + bv.w;
#pragma unroll
    for (int j = 0; j < 8; j++) f[j] = f[j] > 0.f ? f[j] : (__expf(f[j]) - 1.0f);

    float a0 = 0.f, a1 = 0.f, a2 = 0.f;
    int kbase = lane * 8;
#pragma unroll
    for (int j = 0; j < 8; j++) {
        const float* w = W2 + (size_t)(kbase + j) * OC;
        a0 = fmaf(f[j], w[0], a0);
        a1 = fmaf(f[j], w[1], a1);
        a2 = fmaf(f[j], w[2], a2);
    }
#pragma unroll
    for (int off = 16; off; off >>= 1) {
        a0 += __shfl_xor_sync(0xffffffffu, a0, off);
        a1 += __shfl_xor_sync(0xffffffffu, a1, off);
        a2 += __shfl_xor_sync(0xffffffffu, a2, off);
    }
    if (lane == 0) {
        *(float4*)(g_h2 + (size_t)n * 4) = make_float4(a0, a1, a2, 0.f);
        g_als2[n] = a0 * as2[0] + a1 * as2[1] + a2 * as2[2];
        g_ald2[n] = a0 * ad2[0] + a1 * ad2[1] + a2 * ad2[2];
    }
}

// ---------------- layer-2 aggregation (thread per node) + log_softmax ----------------
__global__ void agg2_kernel(const float* __restrict__ b2, float* __restrict__ out) {
    int n = blockIdx.x * blockDim.x + threadIdx.x;
    if (n >= NN) return;
    int beg = g_off[n], end = g_off[n + 1];
    float ald = g_ald2[n];
    float a0 = 0.f, a1 = 0.f, a2 = 0.f, den = 0.f;
    for (int i = beg; i < end; i++) {
        int s = g_esrc[i];
        float w = __expf(lrelu(g_als2[s] + ald));
        float4 hv = *(const float4*)(g_h2 + (size_t)s * 4);
        a0 = fmaf(hv.x, w, a0);
        a1 = fmaf(hv.y, w, a1);
        a2 = fmaf(hv.z, w, a2);
        den += w;
    }
    float inv = 1.0f / fmaxf(den, 1e-16f);
    float o0 = a0 * inv + b2[0];
    float o1 = a1 * inv + b2[1];
    float o2 = a2 * inv + b2[2];
    float m = fmaxf(o0, fmaxf(o1, o2));
    float l = logf(expf(o0 - m) + expf(o1 - m) + expf(o2 - m)) + m;
    out[n * 3 + 0] = o0 - l;
    out[n * 3 + 1] = o1 - l;
    out[n * 3 + 2] = o2 - l;
}

extern "C" void kernel_launch(void* const* d_in, const int* in_sizes, int n_in,
                              void* d_out, int out_size) {
    const float* x   = (const float*)d_in[0];
    const void*  ei  = d_in[1];
    const float* W1  = (const float*)d_in[2];
    const float* as1 = (const float*)d_in[3];
    const float* ad1 = (const float*)d_in[4];
    const float* b1  = (const float*)d_in[5];
    const float* W2  = (const float*)d_in[6];
    const float* as2 = (const float*)d_in[7];
    const float* ad2 = (const float*)d_in[8];
    const float* b2  = (const float*)d_in[9];

    zero_cnt_kernel<<<(NN + 255) / 256, 256>>>();
    detect_kernel<<<1, 32>>>((const unsigned*)ei);
    convert_kernel<<<(NE + 255) / 256, 256>>>(ei);
    scan1_kernel<<<SCAN_NB, 1024>>>();
    scan2_kernel<<<1, 64>>>();
    scan3_kernel<<<SCAN_NB, 1024>>>();
    scatter_kernel<<<(NE + 255) / 256, 256>>>();

    gemm1_kernel<<<dim3((NN + 127) / 128, F1 / 128), 256>>>(x, W1);
    att1_kernel<<<(NN + 7) / 8, 256>>>(as1, ad1);
    agg1_kernel<<<(NN + 7) / 8, 256>>>(b1, W2, as2, ad2);
    agg2_kernel<<<(NN + 255) / 256, 256>>>(b2, (float*)d_out);
}